// round 14
// baseline (speedup 1.0000x reference)
#include <cuda_runtime.h>
#include <cstdint>

#define BB 4
#define TT 2048
#define CC 1024
#define HH 16
#define DHH 64
#define M_TOT (BB*TT)   // 8192

// Scratch (static device globals). All tensors below hold tf32-rounded values.
__device__ float g_q[BB*HH*TT*DHH];
__device__ float g_k[BB*HH*TT*DHH];
__device__ float g_v[BB*HH*TT*DHH];
__device__ float g_att[BB*TT*CC];
__device__ float g_Wt[3*CC*CC];      // qkv weights transposed: [sel][n=h*64+d][k=c], Wq pre-scaled by 0.125
__device__ float g_Wp[CC*CC];        // Wo as tf32 (already [n][k] row-major)
__device__ float g_xc[M_TOT*CC];     // x as tf32

// ================= helpers =================
__device__ __forceinline__ float to_tf32(float x) {
    uint32_t u;
    asm("cvt.rna.tf32.f32 %0, %1;" : "=r"(u) : "f"(x));
    return __uint_as_float(u);
}

__device__ __forceinline__ void mma_tf32(float c[4],
                                         uint32_t a0, uint32_t a1, uint32_t a2, uint32_t a3,
                                         uint32_t b0, uint32_t b1) {
    asm volatile(
        "mma.sync.aligned.m16n8k8.row.col.f32.tf32.tf32.f32 "
        "{%0,%1,%2,%3}, {%4,%5,%6,%7}, {%8,%9}, {%0,%1,%2,%3};"
        : "+f"(c[0]), "+f"(c[1]), "+f"(c[2]), "+f"(c[3])
        : "r"(a0), "r"(a1), "r"(a2), "r"(a3), "r"(b0), "r"(b1));
}

__device__ __forceinline__ void cp16(uint32_t dst_smem, const void* src) {
    asm volatile("cp.async.cg.shared.global [%0], [%1], 16;" :: "r"(dst_smem), "l"(src));
}
#define CP_COMMIT() asm volatile("cp.async.commit_group;" ::: "memory")
#define CP_WAIT(N)  asm volatile("cp.async.wait_group %0;" :: "n"(N) : "memory")

// ============================================================
// Kernel 0a: elementwise tf32 conversion (x -> g_xc, Wo -> g_Wp)
// ============================================================
__global__ void __launch_bounds__(256) conv_tf32(const float4* __restrict__ src,
                                                 float4* __restrict__ dst)
{
    int i = blockIdx.x * 256 + threadIdx.x;
    float4 v = src[i];
    v.x = to_tf32(v.x); v.y = to_tf32(v.y);
    v.z = to_tf32(v.z); v.w = to_tf32(v.w);
    dst[i] = v;
}

// ============================================================
// Kernel 0b: weight transpose + tf32 (+0.125 fold into Wq)
// g_Wt[sel][n=h*64+d][k=c] = tf32(W_sel[h][c][d] * (sel==0 ? 0.125 : 1))
// ============================================================
__global__ void __launch_bounds__(256) wt_kernel(
    const float* __restrict__ Wq, const float* __restrict__ Wk, const float* __restrict__ Wv)
{
    __shared__ float t[32][33];
    const int sel = blockIdx.z;
    const float* W = (sel == 0) ? Wq : (sel == 1 ? Wk : Wv);
    const float scale = (sel == 0) ? 0.125f : 1.0f;
    float* out = g_Wt + (size_t)sel * CC * CC;
    const int head = blockIdx.y >> 1;
    const int d0 = (blockIdx.y & 1) * 32;
    const int k0 = blockIdx.x * 32;
    const int tx = threadIdx.x, ty = threadIdx.y;
#pragma unroll
    for (int j = 0; j < 4; j++) {
        int k = k0 + ty + j * 8;
        t[ty + j * 8][tx] = to_tf32(W[((size_t)head * CC + k) * DHH + d0 + tx] * scale);
    }
    __syncthreads();
#pragma unroll
    for (int j = 0; j < 4; j++) {
        int n = head * 64 + d0 + ty + j * 8;
        out[(size_t)n * CC + k0 + tx] = t[tx][ty + j * 8];
    }
}

// ============================================================
// mma.sync tf32 GEMM, 128x128 CTA tile, 8 warps, warp tile 64x32.
// cp.async 3-stage pipeline. All operands pre-converted tf32.
// MODE 0: qkv (A=g_xc, B=g_Wt[sel], out=g_q/g_k/g_v tf32 [B,H,T,DH])
// MODE 1: proj (A=g_att, B=g_Wp, out=final fp32 +bias)
// ============================================================
#define KT 32
#define NSTAGE (CC / KT)        // 32
#define ASTR 36
#define TILE_F (128 * ASTR)     // 4608 floats
#define GEMM_SMEM (3 * 2 * TILE_F * 4)   // 110592 B

template <int MODE>
__global__ void __launch_bounds__(256) gemm_mma(
    const float* __restrict__ Bext, const float* __restrict__ bias,
    float* __restrict__ outp)
{
    extern __shared__ __align__(16) float smem[];
    const uint32_t smb = (uint32_t)__cvta_generic_to_shared(smem);
    const int tid = threadIdx.x;
    const int lane = tid & 31, wid = tid >> 5;
    const int g = lane >> 2;
    const int tg = lane & 3;
    const int warp_m = (wid & 1) * 64;
    const int warp_n = (wid >> 1) * 32;
    const int m0 = blockIdx.x * 128;

    int n0;
    const float* Ap;
    const float* Bp;
    float* op;
    if (MODE == 0) {
        const int sel = blockIdx.y >> 3;
        n0 = (blockIdx.y & 7) * 128;
        Ap = g_xc;
        Bp = g_Wt + (size_t)sel * CC * CC;
        op = (sel == 0) ? g_q : (sel == 1 ? g_k : g_v);
    } else {
        n0 = blockIdx.y * 128;
        Ap = g_att;
        Bp = Bext;
        op = outp;
    }

    float acc[4][4][4];
#pragma unroll
    for (int im = 0; im < 4; im++)
#pragma unroll
        for (int in = 0; in < 4; in++)
#pragma unroll
            for (int c = 0; c < 4; c++) acc[im][in][c] = 0.0f;

    auto issue_stage = [&](int s, int buf) {
        const int k0 = s * KT;
        const uint32_t dA = smb + (uint32_t)(buf * 2 * TILE_F) * 4u;
        const uint32_t dB = dA + (uint32_t)TILE_F * 4u;
#pragma unroll
        for (int j = 0; j < 4; j++) {
            int idx = tid + j * 256;
            int r = idx >> 3, c4 = (idx & 7) << 2;
            cp16(dA + (uint32_t)(r * ASTR + c4) * 4u, &Ap[(size_t)(m0 + r) * CC + k0 + c4]);
            cp16(dB + (uint32_t)(r * ASTR + c4) * 4u, &Bp[(size_t)(n0 + r) * CC + k0 + c4]);
        }
        CP_COMMIT();
    };

    issue_stage(0, 0);
    issue_stage(1, 1);
    issue_stage(2, 2);

    for (int s = 0; s < NSTAGE; s++) {
        const int rem = NSTAGE - 1 - s;
        if (rem >= 2) CP_WAIT(2);
        else if (rem == 1) CP_WAIT(1);
        else CP_WAIT(0);
        __syncthreads();

        const float* sA = smem + (s % 3) * 2 * TILE_F;
        const float* sB = sA + TILE_F;
#pragma unroll
        for (int k8 = 0; k8 < 4; k8++) {
            const int kk = k8 * 8 + tg;
            uint32_t bf[4][2];
#pragma unroll
            for (int in = 0; in < 4; in++) {
                int n = warp_n + in * 8 + g;
                bf[in][0] = __float_as_uint(sB[n * ASTR + kk]);
                bf[in][1] = __float_as_uint(sB[n * ASTR + kk + 4]);
            }
#pragma unroll
            for (int im = 0; im < 4; im++) {
                int m = warp_m + im * 16 + g;
                uint32_t a0 = __float_as_uint(sA[m * ASTR + kk]);
                uint32_t a1 = __float_as_uint(sA[(m + 8) * ASTR + kk]);
                uint32_t a2 = __float_as_uint(sA[m * ASTR + kk + 4]);
                uint32_t a3 = __float_as_uint(sA[(m + 8) * ASTR + kk + 4]);
#pragma unroll
                for (int in = 0; in < 4; in++)
                    mma_tf32(acc[im][in], a0, a1, a2, a3, bf[in][0], bf[in][1]);
            }
        }
        __syncthreads();
        if (s + 3 < NSTAGE) issue_stage(s + 3, s % 3);
    }

    // ---- epilogue ----
#pragma unroll
    for (int im = 0; im < 4; im++) {
#pragma unroll
        for (int in = 0; in < 4; in++) {
            int row0 = m0 + warp_m + im * 16 + g;
            int col = n0 + warp_n + in * 8 + tg * 2;
            if (MODE == 0) {
                int head = col >> 6, d = col & 63;
#pragma unroll
                for (int h = 0; h < 2; h++) {
                    int m = row0 + h * 8;
                    int b = m >> 11, t = m & 2047;
                    float2 v = make_float2(to_tf32(acc[im][in][h * 2]),
                                           to_tf32(acc[im][in][h * 2 + 1]));
                    *reinterpret_cast<float2*>(
                        &op[((size_t)(b * HH + head) * TT + t) * DHH + d]) = v;
                }
            } else {
                float b0 = bias[col], b1 = bias[col + 1];
#pragma unroll
                for (int h = 0; h < 2; h++) {
                    int m = row0 + h * 8;
                    float2 v = make_float2(acc[im][in][h * 2] + b0, acc[im][in][h * 2 + 1] + b1);
                    *reinterpret_cast<float2*>(&op[(size_t)m * CC + col]) = v;
                }
            }
        }
    }
}

// ============================================================
// Kernel 2: causal flash attention on mma.sync tf32, cp.async K/V prefetch.
// BR=BC=64, 4 warps x 16 q-rows. Q pre-scaled (0.125 folded into Wq).
// ============================================================
#define QS_STR 68
#define VS_STR 72
#define Q_OFF  0
#define P_OFF  (64 * QS_STR)                 // 4352
#define K_OFF  (2 * 64 * QS_STR)             // 8704
#define V_OFF  (K_OFF + 2 * 64 * QS_STR)     // 17408
#define KBUF_F (64 * QS_STR)                 // 4352
#define VBUF_F (64 * VS_STR)                 // 4608
#define ATTN_SMEM ((V_OFF + 2 * VBUF_F) * 4) // 106496 B

__global__ void __launch_bounds__(128) attn_kernel()
{
    extern __shared__ __align__(16) float sm[];
    const uint32_t smb = (uint32_t)__cvta_generic_to_shared(sm);
    float* qs = sm + Q_OFF;
    float* ps = sm + P_OFF;

    const int tid = threadIdx.x;
    const int lane = tid & 31, w = tid >> 5;
    const int g = lane >> 2, tg = lane & 3;
    const int qt = blockIdx.x, bh = blockIdx.y;
    const size_t base = (size_t)bh * TT * DHH;

    const int rA = w * 16 + g;
    const int rB = rA + 8;

    auto issue_kv = [&](int kt_, int b) {
        const uint32_t kd = smb + (uint32_t)(K_OFF + b * KBUF_F) * 4u;
        const uint32_t vd = smb + (uint32_t)(V_OFF + b * VBUF_F) * 4u;
#pragma unroll
        for (int j = 0; j < 8; j++) {
            int idx = tid + j * 128;
            int r = idx >> 4, c4 = (idx & 15) << 2;
            cp16(kd + (uint32_t)(r * QS_STR + c4) * 4u,
                 &g_k[base + (size_t)(kt_ * 64 + r) * DHH + c4]);
            cp16(vd + (uint32_t)(r * VS_STR + c4) * 4u,
                 &g_v[base + (size_t)(kt_ * 64 + r) * DHH + c4]);
        }
        CP_COMMIT();
    };

    // prologue: Q + KV(0) as one group
#pragma unroll
    for (int j = 0; j < 8; j++) {
        int idx = tid + j * 128;
        int r = idx >> 4, c4 = (idx & 15) << 2;
        cp16(smb + (uint32_t)(Q_OFF + r * QS_STR + c4) * 4u,
             &g_q[base + (size_t)(qt * 64 + r) * DHH + c4]);
    }
    issue_kv(0, 0);

    float oacc[8][4];
#pragma unroll
    for (int in = 0; in < 8; in++)
#pragma unroll
        for (int c = 0; c < 4; c++) oacc[in][c] = 0.0f;
    float mA = -1e30f, mB = -1e30f, lA = 0.0f, lB = 0.0f;

    for (int kt = 0; kt <= qt; kt++) {
        const int b = kt & 1;
        if (kt + 1 <= qt) {
            issue_kv(kt + 1, b ^ 1);   // buf b^1: last read finished before end-of-iter barrier of kt-1
            CP_WAIT(1);
        } else {
            CP_WAIT(0);
        }
        __syncthreads();
        const float* ks = sm + K_OFF + b * KBUF_F;
        const float* vs = sm + V_OFF + b * VBUF_F;

        // ---- S = Q K^T ----
        float sacc[8][4];
#pragma unroll
        for (int in = 0; in < 8; in++)
#pragma unroll
            for (int c = 0; c < 4; c++) sacc[in][c] = 0.0f;

#pragma unroll
        for (int k8 = 0; k8 < 8; k8++) {
            const int kk = k8 * 8 + tg;
            uint32_t a0 = __float_as_uint(qs[rA * QS_STR + kk]);
            uint32_t a1 = __float_as_uint(qs[rB * QS_STR + kk]);
            uint32_t a2 = __float_as_uint(qs[rA * QS_STR + kk + 4]);
            uint32_t a3 = __float_as_uint(qs[rB * QS_STR + kk + 4]);
#pragma unroll
            for (int in = 0; in < 8; in++) {
                uint32_t b0 = __float_as_uint(ks[(in * 8 + g) * QS_STR + kk]);
                uint32_t b1 = __float_as_uint(ks[(in * 8 + g) * QS_STR + kk + 4]);
                mma_tf32(sacc[in], a0, a1, a2, a3, b0, b1);
            }
        }

        // ---- causal mask ----
        if (kt == qt) {
#pragma unroll
            for (int in = 0; in < 8; in++) {
                int c0 = in * 8 + tg * 2;
                if (c0 > rA)     sacc[in][0] = -1e30f;
                if (c0 + 1 > rA) sacc[in][1] = -1e30f;
                if (c0 > rB)     sacc[in][2] = -1e30f;
                if (c0 + 1 > rB) sacc[in][3] = -1e30f;
            }
        }

        // ---- online softmax (quad-local) ----
        float mlA = -1e30f, mlB = -1e30f;
#pragma unroll
        for (int in = 0; in < 8; in++) {
            mlA = fmaxf(mlA, fmaxf(sacc[in][0], sacc[in][1]));
            mlB = fmaxf(mlB, fmaxf(sacc[in][2], sacc[in][3]));
        }
#pragma unroll
        for (int msk = 1; msk < 4; msk <<= 1) {
            mlA = fmaxf(mlA, __shfl_xor_sync(0xffffffffu, mlA, msk));
            mlB = fmaxf(mlB, __shfl_xor_sync(0xffffffffu, mlB, msk));
        }
        float mnA = fmaxf(mA, mlA), mnB = fmaxf(mB, mlB);
        float facA = __expf(mA - mnA), facB = __expf(mB - mnB);
        mA = mnA; mB = mnB;

        float rsA = 0.0f, rsB = 0.0f;
#pragma unroll
        for (int in = 0; in < 8; in++) {
            float p0 = __expf(sacc[in][0] - mnA);
            float p1 = __expf(sacc[in][1] - mnA);
            float p2 = __expf(sacc[in][2] - mnB);
            float p3 = __expf(sacc[in][3] - mnB);
            rsA += p0 + p1; rsB += p2 + p3;
            int col = in * 8 + tg * 2;
            *reinterpret_cast<float2*>(&ps[rA * QS_STR + col]) =
                make_float2(to_tf32(p0), to_tf32(p1));
            *reinterpret_cast<float2*>(&ps[rB * QS_STR + col]) =
                make_float2(to_tf32(p2), to_tf32(p3));
        }
#pragma unroll
        for (int msk = 1; msk < 4; msk <<= 1) {
            rsA += __shfl_xor_sync(0xffffffffu, rsA, msk);
            rsB += __shfl_xor_sync(0xffffffffu, rsB, msk);
        }
        lA = lA * facA + rsA;
        lB = lB * facB + rsB;
#pragma unroll
        for (int in = 0; in < 8; in++) {
            oacc[in][0] *= facA; oacc[in][1] *= facA;
            oacc[in][2] *= facB; oacc[in][3] *= facB;
        }
        __syncthreads();   // ps visible

        // ---- O += P V ----
#pragma unroll
        for (int k8 = 0; k8 < 8; k8++) {
            const int kk = k8 * 8 + tg;
            uint32_t a0 = __float_as_uint(ps[rA * QS_STR + kk]);
            uint32_t a1 = __float_as_uint(ps[rB * QS_STR + kk]);
            uint32_t a2 = __float_as_uint(ps[rA * QS_STR + kk + 4]);
            uint32_t a3 = __float_as_uint(ps[rB * QS_STR + kk + 4]);
#pragma unroll
            for (int in = 0; in < 8; in++) {
                uint32_t b0 = __float_as_uint(vs[kk * VS_STR + in * 8 + g]);
                uint32_t b1 = __float_as_uint(vs[(kk + 4) * VS_STR + in * 8 + g]);
                mma_tf32(oacc[in], a0, a1, a2, a3, b0, b1);
            }
        }
        __syncthreads();   // PV reads of buf b + ps done (protects next iter's writes)
    }

    // ---- epilogue (tf32 values for proj A operand) ----
    const float invA = 1.0f / lA, invB = 1.0f / lB;
    const int bb = bh >> 4, hh = bh & 15;
    const int rowA = qt * 64 + rA;
#pragma unroll
    for (int in = 0; in < 8; in++) {
        int col = hh * 64 + in * 8 + tg * 2;
        *reinterpret_cast<float2*>(&g_att[(size_t)(bb * TT + rowA) * CC + col]) =
            make_float2(to_tf32(oacc[in][0] * invA), to_tf32(oacc[in][1] * invA));
        *reinterpret_cast<float2*>(&g_att[(size_t)(bb * TT + rowA + 8) * CC + col]) =
            make_float2(to_tf32(oacc[in][2] * invB), to_tf32(oacc[in][3] * invB));
    }
}

// ============================================================
extern "C" void kernel_launch(void* const* d_in, const int* in_sizes, int n_in,
                              void* d_out, int out_size)
{
    const float* x  = (const float*)d_in[0];
    const float* Wq = (const float*)d_in[1];
    const float* Wk = (const float*)d_in[2];
    const float* Wv = (const float*)d_in[3];
    const float* Wo = (const float*)d_in[4];
    const float* bo = (const float*)d_in[5];
    float* out = (float*)d_out;

    cudaFuncSetAttribute(gemm_mma<0>, cudaFuncAttributeMaxDynamicSharedMemorySize, GEMM_SMEM);
    cudaFuncSetAttribute(gemm_mma<1>, cudaFuncAttributeMaxDynamicSharedMemorySize, GEMM_SMEM);
    cudaFuncSetAttribute(attn_kernel, cudaFuncAttributeMaxDynamicSharedMemorySize, ATTN_SMEM);

    float* g_xc_p;  cudaGetSymbolAddress((void**)&g_xc_p, g_xc);
    float* g_Wp_p;  cudaGetSymbolAddress((void**)&g_Wp_p, g_Wp);

    conv_tf32<<<M_TOT * CC / 1024, 256>>>((const float4*)x, (float4*)g_xc_p);
    conv_tf32<<<CC * CC / 1024, 256>>>((const float4*)Wo, (float4*)g_Wp_p);
    wt_kernel<<<dim3(32, 32, 3), dim3(32, 8)>>>(Wq, Wk, Wv);
    gemm_mma<0><<<dim3(M_TOT / 128, 24), 256, GEMM_SMEM>>>(nullptr, nullptr, nullptr);
    attn_kernel<<<dim3(TT / 64, BB * HH), 128, ATTN_SMEM>>>();
    gemm_mma<1><<<dim3(M_TOT / 128, 8), 256, GEMM_SMEM>>>(g_Wp_p, bo, out);
}

// round 15
// speedup vs baseline: 1.0024x; 1.0024x over previous
#include <cuda_runtime.h>
#include <cstdint>

#define BB 4
#define TT 2048
#define CC 1024
#define HH 16
#define DHH 64
#define M_TOT (BB*TT)   // 8192

// Scratch (static device globals). All tensors below hold tf32-rounded values.
__device__ float g_q[BB*HH*TT*DHH];
__device__ float g_k[BB*HH*TT*DHH];
__device__ float g_v[BB*HH*TT*DHH];
__device__ float g_att[BB*TT*CC];
__device__ float g_Wt[3*CC*CC];      // qkv weights transposed: [sel][n=h*64+d][k=c], Wq pre-scaled by 0.125
__device__ float g_Wp[CC*CC];        // Wo as tf32 (already [n][k] row-major)
__device__ float g_xc[M_TOT*CC];     // x as tf32

// ================= helpers =================
__device__ __forceinline__ float to_tf32(float x) {
    uint32_t u;
    asm("cvt.rna.tf32.f32 %0, %1;" : "=r"(u) : "f"(x));
    return __uint_as_float(u);
}

__device__ __forceinline__ void mma_tf32(float c[4],
                                         uint32_t a0, uint32_t a1, uint32_t a2, uint32_t a3,
                                         uint32_t b0, uint32_t b1) {
    asm volatile(
        "mma.sync.aligned.m16n8k8.row.col.f32.tf32.tf32.f32 "
        "{%0,%1,%2,%3}, {%4,%5,%6,%7}, {%8,%9}, {%0,%1,%2,%3};"
        : "+f"(c[0]), "+f"(c[1]), "+f"(c[2]), "+f"(c[3])
        : "r"(a0), "r"(a1), "r"(a2), "r"(a3), "r"(b0), "r"(b1));
}

__device__ __forceinline__ void cp16(uint32_t dst_smem, const void* src) {
    asm volatile("cp.async.cg.shared.global [%0], [%1], 16;" :: "r"(dst_smem), "l"(src));
}
#define CP_COMMIT() asm volatile("cp.async.commit_group;" ::: "memory")
#define CP_WAIT(N)  asm volatile("cp.async.wait_group %0;" :: "n"(N) : "memory")

// ============================================================
// Kernel 0a: elementwise tf32 conversion (x -> g_xc, Wo -> g_Wp)
// ============================================================
__global__ void __launch_bounds__(256) conv_tf32(const float4* __restrict__ src,
                                                 float4* __restrict__ dst)
{
    int i = blockIdx.x * 256 + threadIdx.x;
    float4 v = src[i];
    v.x = to_tf32(v.x); v.y = to_tf32(v.y);
    v.z = to_tf32(v.z); v.w = to_tf32(v.w);
    dst[i] = v;
}

// ============================================================
// Kernel 0b: weight transpose + tf32 (+0.125 fold into Wq)
// g_Wt[sel][n=h*64+d][k=c] = tf32(W_sel[h][c][d] * (sel==0 ? 0.125 : 1))
// ============================================================
__global__ void __launch_bounds__(256) wt_kernel(
    const float* __restrict__ Wq, const float* __restrict__ Wk, const float* __restrict__ Wv)
{
    __shared__ float t[32][33];
    const int sel = blockIdx.z;
    const float* W = (sel == 0) ? Wq : (sel == 1 ? Wk : Wv);
    const float scale = (sel == 0) ? 0.125f : 1.0f;
    float* out = g_Wt + (size_t)sel * CC * CC;
    const int head = blockIdx.y >> 1;
    const int d0 = (blockIdx.y & 1) * 32;
    const int k0 = blockIdx.x * 32;
    const int tx = threadIdx.x, ty = threadIdx.y;
#pragma unroll
    for (int j = 0; j < 4; j++) {
        int k = k0 + ty + j * 8;
        t[ty + j * 8][tx] = to_tf32(W[((size_t)head * CC + k) * DHH + d0 + tx] * scale);
    }
    __syncthreads();
#pragma unroll
    for (int j = 0; j < 4; j++) {
        int n = head * 64 + d0 + ty + j * 8;
        out[(size_t)n * CC + k0 + tx] = t[tx][ty + j * 8];
    }
}

// ============================================================
// mma.sync tf32 GEMM, 128x128 CTA tile, 8 warps, warp tile 64x32.
// cp.async 3-stage pipeline. All operands pre-converted tf32.
// MODE 0: qkv (A=g_xc, B=g_Wt[sel], out=g_q/g_k/g_v tf32 [B,H,T,DH])
// MODE 1: proj (A=g_att, B=g_Wp, out=final fp32 +bias)
// ============================================================
#define KT 32
#define NSTAGE (CC / KT)        // 32
#define ASTR 36
#define TILE_F (128 * ASTR)     // 4608 floats
#define GEMM_SMEM (3 * 2 * TILE_F * 4)   // 110592 B

template <int MODE>
__global__ void __launch_bounds__(256) gemm_mma(
    const float* __restrict__ Bext, const float* __restrict__ bias,
    float* __restrict__ outp)
{
    extern __shared__ __align__(16) float smem[];
    const uint32_t smb = (uint32_t)__cvta_generic_to_shared(smem);
    const int tid = threadIdx.x;
    const int lane = tid & 31, wid = tid >> 5;
    const int g = lane >> 2;
    const int tg = lane & 3;
    const int warp_m = (wid & 1) * 64;
    const int warp_n = (wid >> 1) * 32;
    const int m0 = blockIdx.x * 128;

    int n0;
    const float* Ap;
    const float* Bp;
    float* op;
    if (MODE == 0) {
        const int sel = blockIdx.y >> 3;
        n0 = (blockIdx.y & 7) * 128;
        Ap = g_xc;
        Bp = g_Wt + (size_t)sel * CC * CC;
        op = (sel == 0) ? g_q : (sel == 1 ? g_k : g_v);
    } else {
        n0 = blockIdx.y * 128;
        Ap = g_att;
        Bp = Bext;
        op = outp;
    }

    float acc[4][4][4];
#pragma unroll
    for (int im = 0; im < 4; im++)
#pragma unroll
        for (int in = 0; in < 4; in++)
#pragma unroll
            for (int c = 0; c < 4; c++) acc[im][in][c] = 0.0f;

    auto issue_stage = [&](int s, int buf) {
        const int k0 = s * KT;
        const uint32_t dA = smb + (uint32_t)(buf * 2 * TILE_F) * 4u;
        const uint32_t dB = dA + (uint32_t)TILE_F * 4u;
#pragma unroll
        for (int j = 0; j < 4; j++) {
            int idx = tid + j * 256;
            int r = idx >> 3, c4 = (idx & 7) << 2;
            cp16(dA + (uint32_t)(r * ASTR + c4) * 4u, &Ap[(size_t)(m0 + r) * CC + k0 + c4]);
            cp16(dB + (uint32_t)(r * ASTR + c4) * 4u, &Bp[(size_t)(n0 + r) * CC + k0 + c4]);
        }
        CP_COMMIT();
    };

    issue_stage(0, 0);
    issue_stage(1, 1);
    issue_stage(2, 2);

    for (int s = 0; s < NSTAGE; s++) {
        const int rem = NSTAGE - 1 - s;
        if (rem >= 2) CP_WAIT(2);
        else if (rem == 1) CP_WAIT(1);
        else CP_WAIT(0);
        __syncthreads();

        const float* sA = smem + (s % 3) * 2 * TILE_F;
        const float* sB = sA + TILE_F;
#pragma unroll
        for (int k8 = 0; k8 < 4; k8++) {
            const int kk = k8 * 8 + tg;
            uint32_t bf[4][2];
#pragma unroll
            for (int in = 0; in < 4; in++) {
                int n = warp_n + in * 8 + g;
                bf[in][0] = __float_as_uint(sB[n * ASTR + kk]);
                bf[in][1] = __float_as_uint(sB[n * ASTR + kk + 4]);
            }
#pragma unroll
            for (int im = 0; im < 4; im++) {
                int m = warp_m + im * 16 + g;
                uint32_t a0 = __float_as_uint(sA[m * ASTR + kk]);
                uint32_t a1 = __float_as_uint(sA[(m + 8) * ASTR + kk]);
                uint32_t a2 = __float_as_uint(sA[m * ASTR + kk + 4]);
                uint32_t a3 = __float_as_uint(sA[(m + 8) * ASTR + kk + 4]);
#pragma unroll
                for (int in = 0; in < 4; in++)
                    mma_tf32(acc[im][in], a0, a1, a2, a3, bf[in][0], bf[in][1]);
            }
        }
        __syncthreads();
        if (s + 3 < NSTAGE) issue_stage(s + 3, s % 3);
    }

    // ---- epilogue ----
#pragma unroll
    for (int im = 0; im < 4; im++) {
#pragma unroll
        for (int in = 0; in < 4; in++) {
            int row0 = m0 + warp_m + im * 16 + g;
            int col = n0 + warp_n + in * 8 + tg * 2;
            if (MODE == 0) {
                int head = col >> 6, d = col & 63;
#pragma unroll
                for (int h = 0; h < 2; h++) {
                    int m = row0 + h * 8;
                    int b = m >> 11, t = m & 2047;
                    float2 v = make_float2(to_tf32(acc[im][in][h * 2]),
                                           to_tf32(acc[im][in][h * 2 + 1]));
                    *reinterpret_cast<float2*>(
                        &op[((size_t)(b * HH + head) * TT + t) * DHH + d]) = v;
                }
            } else {
                float b0 = bias[col], b1 = bias[col + 1];
#pragma unroll
                for (int h = 0; h < 2; h++) {
                    int m = row0 + h * 8;
                    float2 v = make_float2(acc[im][in][h * 2] + b0, acc[im][in][h * 2 + 1] + b1);
                    *reinterpret_cast<float2*>(&op[(size_t)m * CC + col]) = v;
                }
            }
        }
    }
}

// ============================================================
// Kernel 2: causal flash attention on mma.sync tf32, cp.async K/V prefetch.
// BR=BC=64, 4 warps x 16 q-rows. Q pre-scaled (0.125 folded into Wq).
// ============================================================
#define QS_STR 68
#define VS_STR 72
#define Q_OFF  0
#define P_OFF  (64 * QS_STR)                 // 4352
#define K_OFF  (2 * 64 * QS_STR)             // 8704
#define V_OFF  (K_OFF + 2 * 64 * QS_STR)     // 17408
#define KBUF_F (64 * QS_STR)                 // 4352
#define VBUF_F (64 * VS_STR)                 // 4608
#define ATTN_SMEM ((V_OFF + 2 * VBUF_F) * 4) // 106496 B

__global__ void __launch_bounds__(128) attn_kernel()
{
    extern __shared__ __align__(16) float sm[];
    const uint32_t smb = (uint32_t)__cvta_generic_to_shared(sm);
    float* qs = sm + Q_OFF;
    float* ps = sm + P_OFF;

    const int tid = threadIdx.x;
    const int lane = tid & 31, w = tid >> 5;
    const int g = lane >> 2, tg = lane & 3;
    const int qt = blockIdx.x, bh = blockIdx.y;
    const size_t base = (size_t)bh * TT * DHH;

    const int rA = w * 16 + g;
    const int rB = rA + 8;

    auto issue_kv = [&](int kt_, int b) {
        const uint32_t kd = smb + (uint32_t)(K_OFF + b * KBUF_F) * 4u;
        const uint32_t vd = smb + (uint32_t)(V_OFF + b * VBUF_F) * 4u;
#pragma unroll
        for (int j = 0; j < 8; j++) {
            int idx = tid + j * 128;
            int r = idx >> 4, c4 = (idx & 15) << 2;
            cp16(kd + (uint32_t)(r * QS_STR + c4) * 4u,
                 &g_k[base + (size_t)(kt_ * 64 + r) * DHH + c4]);
            cp16(vd + (uint32_t)(r * VS_STR + c4) * 4u,
                 &g_v[base + (size_t)(kt_ * 64 + r) * DHH + c4]);
        }
        CP_COMMIT();
    };

    // prologue: Q + KV(0) as one group
#pragma unroll
    for (int j = 0; j < 8; j++) {
        int idx = tid + j * 128;
        int r = idx >> 4, c4 = (idx & 15) << 2;
        cp16(smb + (uint32_t)(Q_OFF + r * QS_STR + c4) * 4u,
             &g_q[base + (size_t)(qt * 64 + r) * DHH + c4]);
    }
    issue_kv(0, 0);

    float oacc[8][4];
#pragma unroll
    for (int in = 0; in < 8; in++)
#pragma unroll
        for (int c = 0; c < 4; c++) oacc[in][c] = 0.0f;
    float mA = -1e30f, mB = -1e30f, lA = 0.0f, lB = 0.0f;

    for (int kt = 0; kt <= qt; kt++) {
        const int b = kt & 1;
        if (kt + 1 <= qt) {
            issue_kv(kt + 1, b ^ 1);   // buf b^1: last read finished before end-of-iter barrier of kt-1
            CP_WAIT(1);
        } else {
            CP_WAIT(0);
        }
        __syncthreads();
        const float* ks = sm + K_OFF + b * KBUF_F;
        const float* vs = sm + V_OFF + b * VBUF_F;

        // ---- S = Q K^T ----
        float sacc[8][4];
#pragma unroll
        for (int in = 0; in < 8; in++)
#pragma unroll
            for (int c = 0; c < 4; c++) sacc[in][c] = 0.0f;

#pragma unroll
        for (int k8 = 0; k8 < 8; k8++) {
            const int kk = k8 * 8 + tg;
            uint32_t a0 = __float_as_uint(qs[rA * QS_STR + kk]);
            uint32_t a1 = __float_as_uint(qs[rB * QS_STR + kk]);
            uint32_t a2 = __float_as_uint(qs[rA * QS_STR + kk + 4]);
            uint32_t a3 = __float_as_uint(qs[rB * QS_STR + kk + 4]);
#pragma unroll
            for (int in = 0; in < 8; in++) {
                uint32_t b0 = __float_as_uint(ks[(in * 8 + g) * QS_STR + kk]);
                uint32_t b1 = __float_as_uint(ks[(in * 8 + g) * QS_STR + kk + 4]);
                mma_tf32(sacc[in], a0, a1, a2, a3, b0, b1);
            }
        }

        // ---- causal mask ----
        if (kt == qt) {
#pragma unroll
            for (int in = 0; in < 8; in++) {
                int c0 = in * 8 + tg * 2;
                if (c0 > rA)     sacc[in][0] = -1e30f;
                if (c0 + 1 > rA) sacc[in][1] = -1e30f;
                if (c0 > rB)     sacc[in][2] = -1e30f;
                if (c0 + 1 > rB) sacc[in][3] = -1e30f;
            }
        }

        // ---- online softmax (quad-local) ----
        float mlA = -1e30f, mlB = -1e30f;
#pragma unroll
        for (int in = 0; in < 8; in++) {
            mlA = fmaxf(mlA, fmaxf(sacc[in][0], sacc[in][1]));
            mlB = fmaxf(mlB, fmaxf(sacc[in][2], sacc[in][3]));
        }
#pragma unroll
        for (int msk = 1; msk < 4; msk <<= 1) {
            mlA = fmaxf(mlA, __shfl_xor_sync(0xffffffffu, mlA, msk));
            mlB = fmaxf(mlB, __shfl_xor_sync(0xffffffffu, mlB, msk));
        }
        float mnA = fmaxf(mA, mlA), mnB = fmaxf(mB, mlB);
        float facA = __expf(mA - mnA), facB = __expf(mB - mnB);
        mA = mnA; mB = mnB;

        float rsA = 0.0f, rsB = 0.0f;
#pragma unroll
        for (int in = 0; in < 8; in++) {
            float p0 = __expf(sacc[in][0] - mnA);
            float p1 = __expf(sacc[in][1] - mnA);
            float p2 = __expf(sacc[in][2] - mnB);
            float p3 = __expf(sacc[in][3] - mnB);
            rsA += p0 + p1; rsB += p2 + p3;
            int col = in * 8 + tg * 2;
            *reinterpret_cast<float2*>(&ps[rA * QS_STR + col]) =
                make_float2(to_tf32(p0), to_tf32(p1));
            *reinterpret_cast<float2*>(&ps[rB * QS_STR + col]) =
                make_float2(to_tf32(p2), to_tf32(p3));
        }
#pragma unroll
        for (int msk = 1; msk < 4; msk <<= 1) {
            rsA += __shfl_xor_sync(0xffffffffu, rsA, msk);
            rsB += __shfl_xor_sync(0xffffffffu, rsB, msk);
        }
        lA = lA * facA + rsA;
        lB = lB * facB + rsB;
#pragma unroll
        for (int in = 0; in < 8; in++) {
            oacc[in][0] *= facA; oacc[in][1] *= facA;
            oacc[in][2] *= facB; oacc[in][3] *= facB;
        }
        __syncthreads();   // ps visible

        // ---- O += P V ----
#pragma unroll
        for (int k8 = 0; k8 < 8; k8++) {
            const int kk = k8 * 8 + tg;
            uint32_t a0 = __float_as_uint(ps[rA * QS_STR + kk]);
            uint32_t a1 = __float_as_uint(ps[rB * QS_STR + kk]);
            uint32_t a2 = __float_as_uint(ps[rA * QS_STR + kk + 4]);
            uint32_t a3 = __float_as_uint(ps[rB * QS_STR + kk + 4]);
#pragma unroll
            for (int in = 0; in < 8; in++) {
                uint32_t b0 = __float_as_uint(vs[kk * VS_STR + in * 8 + g]);
                uint32_t b1 = __float_as_uint(vs[(kk + 4) * VS_STR + in * 8 + g]);
                mma_tf32(oacc[in], a0, a1, a2, a3, b0, b1);
            }
        }
        __syncthreads();   // PV reads of buf b + ps done (protects next iter's writes)
    }

    // ---- epilogue (tf32 values for proj A operand) ----
    const float invA = 1.0f / lA, invB = 1.0f / lB;
    const int bb = bh >> 4, hh = bh & 15;
    const int rowA = qt * 64 + rA;
#pragma unroll
    for (int in = 0; in < 8; in++) {
        int col = hh * 64 + in * 8 + tg * 2;
        *reinterpret_cast<float2*>(&g_att[(size_t)(bb * TT + rowA) * CC + col]) =
            make_float2(to_tf32(oacc[in][0] * invA), to_tf32(oacc[in][1] * invA));
        *reinterpret_cast<float2*>(&g_att[(size_t)(bb * TT + rowA + 8) * CC + col]) =
            make_float2(to_tf32(oacc[in][2] * invB), to_tf32(oacc[in][3] * invB));
    }
}

// ============================================================
extern "C" void kernel_launch(void* const* d_in, const int* in_sizes, int n_in,
                              void* d_out, int out_size)
{
    const float* x  = (const float*)d_in[0];
    const float* Wq = (const float*)d_in[1];
    const float* Wk = (const float*)d_in[2];
    const float* Wv = (const float*)d_in[3];
    const float* Wo = (const float*)d_in[4];
    const float* bo = (const float*)d_in[5];
    float* out = (float*)d_out;

    cudaFuncSetAttribute(gemm_mma<0>, cudaFuncAttributeMaxDynamicSharedMemorySize, GEMM_SMEM);
    cudaFuncSetAttribute(gemm_mma<1>, cudaFuncAttributeMaxDynamicSharedMemorySize, GEMM_SMEM);
    cudaFuncSetAttribute(attn_kernel, cudaFuncAttributeMaxDynamicSharedMemorySize, ATTN_SMEM);

    float* g_xc_p;  cudaGetSymbolAddress((void**)&g_xc_p, g_xc);
    float* g_Wp_p;  cudaGetSymbolAddress((void**)&g_Wp_p, g_Wp);

    conv_tf32<<<M_TOT * CC / 1024, 256>>>((const float4*)x, (float4*)g_xc_p);
    conv_tf32<<<CC * CC / 1024, 256>>>((const float4*)Wo, (float4*)g_Wp_p);
    wt_kernel<<<dim3(32, 32, 3), dim3(32, 8)>>>(Wq, Wk, Wv);
    gemm_mma<0><<<dim3(M_TOT / 128, 24), 256, GEMM_SMEM>>>(nullptr, nullptr, nullptr);
    attn_kernel<<<dim3(TT / 64, BB * HH), 128, ATTN_SMEM>>>();
    gemm_mma<1><<<dim3(M_TOT / 128, 8), 256, GEMM_SMEM>>>(g_Wp_p, bo, out);
}

// round 16
// speedup vs baseline: 1.0029x; 1.0005x over previous
#include <cuda_runtime.h>
#include <cstdint>

#define BB 4
#define TT 2048
#define CC 1024
#define HH 16
#define DHH 64
#define M_TOT (BB*TT)   // 8192

// Scratch (static device globals). All tensors below hold tf32-rounded values.
__device__ float g_q[BB*HH*TT*DHH];
__device__ float g_k[BB*HH*TT*DHH];
__device__ float g_v[BB*HH*TT*DHH];
__device__ float g_att[BB*TT*CC];
__device__ float g_Wt[3*CC*CC];      // qkv weights transposed: [sel][n=h*64+d][k=c], Wq pre-scaled by 0.125
__device__ float g_Wp[CC*CC];        // Wo as tf32 (already [n][k] row-major)
__device__ float g_xc[M_TOT*CC];     // x as tf32

// ================= helpers =================
__device__ __forceinline__ float to_tf32(float x) {
    uint32_t u;
    asm("cvt.rna.tf32.f32 %0, %1;" : "=r"(u) : "f"(x));
    return __uint_as_float(u);
}

__device__ __forceinline__ void mma_tf32(float c[4],
                                         uint32_t a0, uint32_t a1, uint32_t a2, uint32_t a3,
                                         uint32_t b0, uint32_t b1) {
    asm volatile(
        "mma.sync.aligned.m16n8k8.row.col.f32.tf32.tf32.f32 "
        "{%0,%1,%2,%3}, {%4,%5,%6,%7}, {%8,%9}, {%0,%1,%2,%3};"
        : "+f"(c[0]), "+f"(c[1]), "+f"(c[2]), "+f"(c[3])
        : "r"(a0), "r"(a1), "r"(a2), "r"(a3), "r"(b0), "r"(b1));
}

__device__ __forceinline__ void cp16(uint32_t dst_smem, const void* src) {
    asm volatile("cp.async.cg.shared.global [%0], [%1], 16;" :: "r"(dst_smem), "l"(src));
}
#define CP_COMMIT() asm volatile("cp.async.commit_group;" ::: "memory")
#define CP_WAIT(N)  asm volatile("cp.async.wait_group %0;" :: "n"(N) : "memory")

// ============================================================
// Kernel 0a: elementwise tf32 conversion (x -> g_xc, Wo -> g_Wp)
// ============================================================
__global__ void __launch_bounds__(256) conv_tf32(const float4* __restrict__ src,
                                                 float4* __restrict__ dst)
{
    int i = blockIdx.x * 256 + threadIdx.x;
    float4 v = src[i];
    v.x = to_tf32(v.x); v.y = to_tf32(v.y);
    v.z = to_tf32(v.z); v.w = to_tf32(v.w);
    dst[i] = v;
}

// ============================================================
// Kernel 0b: weight transpose + tf32 (+0.125 fold into Wq)
// g_Wt[sel][n=h*64+d][k=c] = tf32(W_sel[h][c][d] * (sel==0 ? 0.125 : 1))
// ============================================================
__global__ void __launch_bounds__(256) wt_kernel(
    const float* __restrict__ Wq, const float* __restrict__ Wk, const float* __restrict__ Wv)
{
    __shared__ float t[32][33];
    const int sel = blockIdx.z;
    const float* W = (sel == 0) ? Wq : (sel == 1 ? Wk : Wv);
    const float scale = (sel == 0) ? 0.125f : 1.0f;
    float* out = g_Wt + (size_t)sel * CC * CC;
    const int head = blockIdx.y >> 1;
    const int d0 = (blockIdx.y & 1) * 32;
    const int k0 = blockIdx.x * 32;
    const int tx = threadIdx.x, ty = threadIdx.y;
#pragma unroll
    for (int j = 0; j < 4; j++) {
        int k = k0 + ty + j * 8;
        t[ty + j * 8][tx] = to_tf32(W[((size_t)head * CC + k) * DHH + d0 + tx] * scale);
    }
    __syncthreads();
#pragma unroll
    for (int j = 0; j < 4; j++) {
        int n = head * 64 + d0 + ty + j * 8;
        out[(size_t)n * CC + k0 + tx] = t[tx][ty + j * 8];
    }
}

// ============================================================
// mma.sync tf32 GEMM, 128x128 CTA tile, 8 warps, warp tile 64x32.
// cp.async 3-stage pipeline. All operands pre-converted tf32.
// MODE 0: qkv (A=g_xc, B=g_Wt[sel], out=g_q/g_k/g_v tf32 [B,H,T,DH])
// MODE 1: proj (A=g_att, B=g_Wp, out=final fp32 +bias)
// ============================================================
#define KT 32
#define NSTAGE (CC / KT)        // 32
#define ASTR 36
#define TILE_F (128 * ASTR)     // 4608 floats
#define GEMM_SMEM (3 * 2 * TILE_F * 4)   // 110592 B

template <int MODE>
__global__ void __launch_bounds__(256) gemm_mma(
    const float* __restrict__ Bext, const float* __restrict__ bias,
    float* __restrict__ outp)
{
    extern __shared__ __align__(16) float smem[];
    const uint32_t smb = (uint32_t)__cvta_generic_to_shared(smem);
    const int tid = threadIdx.x;
    const int lane = tid & 31, wid = tid >> 5;
    const int g = lane >> 2;
    const int tg = lane & 3;
    const int warp_m = (wid & 1) * 64;
    const int warp_n = (wid >> 1) * 32;
    const int m0 = blockIdx.x * 128;

    int n0;
    const float* Ap;
    const float* Bp;
    float* op;
    if (MODE == 0) {
        const int sel = blockIdx.y >> 3;
        n0 = (blockIdx.y & 7) * 128;
        Ap = g_xc;
        Bp = g_Wt + (size_t)sel * CC * CC;
        op = (sel == 0) ? g_q : (sel == 1 ? g_k : g_v);
    } else {
        n0 = blockIdx.y * 128;
        Ap = g_att;
        Bp = Bext;
        op = outp;
    }

    float acc[4][4][4];
#pragma unroll
    for (int im = 0; im < 4; im++)
#pragma unroll
        for (int in = 0; in < 4; in++)
#pragma unroll
            for (int c = 0; c < 4; c++) acc[im][in][c] = 0.0f;

    auto issue_stage = [&](int s, int buf) {
        const int k0 = s * KT;
        const uint32_t dA = smb + (uint32_t)(buf * 2 * TILE_F) * 4u;
        const uint32_t dB = dA + (uint32_t)TILE_F * 4u;
#pragma unroll
        for (int j = 0; j < 4; j++) {
            int idx = tid + j * 256;
            int r = idx >> 3, c4 = (idx & 7) << 2;
            cp16(dA + (uint32_t)(r * ASTR + c4) * 4u, &Ap[(size_t)(m0 + r) * CC + k0 + c4]);
            cp16(dB + (uint32_t)(r * ASTR + c4) * 4u, &Bp[(size_t)(n0 + r) * CC + k0 + c4]);
        }
        CP_COMMIT();
    };

    issue_stage(0, 0);
    issue_stage(1, 1);
    issue_stage(2, 2);

    for (int s = 0; s < NSTAGE; s++) {
        const int rem = NSTAGE - 1 - s;
        if (rem >= 2) CP_WAIT(2);
        else if (rem == 1) CP_WAIT(1);
        else CP_WAIT(0);
        __syncthreads();

        const float* sA = smem + (s % 3) * 2 * TILE_F;
        const float* sB = sA + TILE_F;
#pragma unroll
        for (int k8 = 0; k8 < 4; k8++) {
            const int kk = k8 * 8 + tg;
            uint32_t bf[4][2];
#pragma unroll
            for (int in = 0; in < 4; in++) {
                int n = warp_n + in * 8 + g;
                bf[in][0] = __float_as_uint(sB[n * ASTR + kk]);
                bf[in][1] = __float_as_uint(sB[n * ASTR + kk + 4]);
            }
#pragma unroll
            for (int im = 0; im < 4; im++) {
                int m = warp_m + im * 16 + g;
                uint32_t a0 = __float_as_uint(sA[m * ASTR + kk]);
                uint32_t a1 = __float_as_uint(sA[(m + 8) * ASTR + kk]);
                uint32_t a2 = __float_as_uint(sA[m * ASTR + kk + 4]);
                uint32_t a3 = __float_as_uint(sA[(m + 8) * ASTR + kk + 4]);
#pragma unroll
                for (int in = 0; in < 4; in++)
                    mma_tf32(acc[im][in], a0, a1, a2, a3, bf[in][0], bf[in][1]);
            }
        }
        __syncthreads();
        if (s + 3 < NSTAGE) issue_stage(s + 3, s % 3);
    }

    // ---- epilogue ----
#pragma unroll
    for (int im = 0; im < 4; im++) {
#pragma unroll
        for (int in = 0; in < 4; in++) {
            int row0 = m0 + warp_m + im * 16 + g;
            int col = n0 + warp_n + in * 8 + tg * 2;
            if (MODE == 0) {
                int head = col >> 6, d = col & 63;
#pragma unroll
                for (int h = 0; h < 2; h++) {
                    int m = row0 + h * 8;
                    int b = m >> 11, t = m & 2047;
                    float2 v = make_float2(to_tf32(acc[im][in][h * 2]),
                                           to_tf32(acc[im][in][h * 2 + 1]));
                    *reinterpret_cast<float2*>(
                        &op[((size_t)(b * HH + head) * TT + t) * DHH + d]) = v;
                }
            } else {
                float b0 = bias[col], b1 = bias[col + 1];
#pragma unroll
                for (int h = 0; h < 2; h++) {
                    int m = row0 + h * 8;
                    float2 v = make_float2(acc[im][in][h * 2] + b0, acc[im][in][h * 2 + 1] + b1);
                    *reinterpret_cast<float2*>(&op[(size_t)m * CC + col]) = v;
                }
            }
        }
    }
}

// ============================================================
// Kernel 2: causal flash attention on mma.sync tf32, cp.async K/V prefetch.
// BR=BC=64, 4 warps x 16 q-rows. Q pre-scaled (0.125 folded into Wq).
// ============================================================
#define QS_STR 68
#define VS_STR 72
#define Q_OFF  0
#define P_OFF  (64 * QS_STR)                 // 4352
#define K_OFF  (2 * 64 * QS_STR)             // 8704
#define V_OFF  (K_OFF + 2 * 64 * QS_STR)     // 17408
#define KBUF_F (64 * QS_STR)                 // 4352
#define VBUF_F (64 * VS_STR)                 // 4608
#define ATTN_SMEM ((V_OFF + 2 * VBUF_F) * 4) // 106496 B

__global__ void __launch_bounds__(128) attn_kernel()
{
    extern __shared__ __align__(16) float sm[];
    const uint32_t smb = (uint32_t)__cvta_generic_to_shared(sm);
    float* qs = sm + Q_OFF;
    float* ps = sm + P_OFF;

    const int tid = threadIdx.x;
    const int lane = tid & 31, w = tid >> 5;
    const int g = lane >> 2, tg = lane & 3;
    const int qt = blockIdx.x, bh = blockIdx.y;
    const size_t base = (size_t)bh * TT * DHH;

    const int rA = w * 16 + g;
    const int rB = rA + 8;

    auto issue_kv = [&](int kt_, int b) {
        const uint32_t kd = smb + (uint32_t)(K_OFF + b * KBUF_F) * 4u;
        const uint32_t vd = smb + (uint32_t)(V_OFF + b * VBUF_F) * 4u;
#pragma unroll
        for (int j = 0; j < 8; j++) {
            int idx = tid + j * 128;
            int r = idx >> 4, c4 = (idx & 15) << 2;
            cp16(kd + (uint32_t)(r * QS_STR + c4) * 4u,
                 &g_k[base + (size_t)(kt_ * 64 + r) * DHH + c4]);
            cp16(vd + (uint32_t)(r * VS_STR + c4) * 4u,
                 &g_v[base + (size_t)(kt_ * 64 + r) * DHH + c4]);
        }
        CP_COMMIT();
    };

    // prologue: Q + KV(0) as one group
#pragma unroll
    for (int j = 0; j < 8; j++) {
        int idx = tid + j * 128;
        int r = idx >> 4, c4 = (idx & 15) << 2;
        cp16(smb + (uint32_t)(Q_OFF + r * QS_STR + c4) * 4u,
             &g_q[base + (size_t)(qt * 64 + r) * DHH + c4]);
    }
    issue_kv(0, 0);

    float oacc[8][4];
#pragma unroll
    for (int in = 0; in < 8; in++)
#pragma unroll
        for (int c = 0; c < 4; c++) oacc[in][c] = 0.0f;
    float mA = -1e30f, mB = -1e30f, lA = 0.0f, lB = 0.0f;

    for (int kt = 0; kt <= qt; kt++) {
        const int b = kt & 1;
        if (kt + 1 <= qt) {
            issue_kv(kt + 1, b ^ 1);   // buf b^1: last read finished before end-of-iter barrier of kt-1
            CP_WAIT(1);
        } else {
            CP_WAIT(0);
        }
        __syncthreads();
        const float* ks = sm + K_OFF + b * KBUF_F;
        const float* vs = sm + V_OFF + b * VBUF_F;

        // ---- S = Q K^T ----
        float sacc[8][4];
#pragma unroll
        for (int in = 0; in < 8; in++)
#pragma unroll
            for (int c = 0; c < 4; c++) sacc[in][c] = 0.0f;

#pragma unroll
        for (int k8 = 0; k8 < 8; k8++) {
            const int kk = k8 * 8 + tg;
            uint32_t a0 = __float_as_uint(qs[rA * QS_STR + kk]);
            uint32_t a1 = __float_as_uint(qs[rB * QS_STR + kk]);
            uint32_t a2 = __float_as_uint(qs[rA * QS_STR + kk + 4]);
            uint32_t a3 = __float_as_uint(qs[rB * QS_STR + kk + 4]);
#pragma unroll
            for (int in = 0; in < 8; in++) {
                uint32_t b0 = __float_as_uint(ks[(in * 8 + g) * QS_STR + kk]);
                uint32_t b1 = __float_as_uint(ks[(in * 8 + g) * QS_STR + kk + 4]);
                mma_tf32(sacc[in], a0, a1, a2, a3, b0, b1);
            }
        }

        // ---- causal mask ----
        if (kt == qt) {
#pragma unroll
            for (int in = 0; in < 8; in++) {
                int c0 = in * 8 + tg * 2;
                if (c0 > rA)     sacc[in][0] = -1e30f;
                if (c0 + 1 > rA) sacc[in][1] = -1e30f;
                if (c0 > rB)     sacc[in][2] = -1e30f;
                if (c0 + 1 > rB) sacc[in][3] = -1e30f;
            }
        }

        // ---- online softmax (quad-local) ----
        float mlA = -1e30f, mlB = -1e30f;
#pragma unroll
        for (int in = 0; in < 8; in++) {
            mlA = fmaxf(mlA, fmaxf(sacc[in][0], sacc[in][1]));
            mlB = fmaxf(mlB, fmaxf(sacc[in][2], sacc[in][3]));
        }
#pragma unroll
        for (int msk = 1; msk < 4; msk <<= 1) {
            mlA = fmaxf(mlA, __shfl_xor_sync(0xffffffffu, mlA, msk));
            mlB = fmaxf(mlB, __shfl_xor_sync(0xffffffffu, mlB, msk));
        }
        float mnA = fmaxf(mA, mlA), mnB = fmaxf(mB, mlB);
        float facA = __expf(mA - mnA), facB = __expf(mB - mnB);
        mA = mnA; mB = mnB;

        float rsA = 0.0f, rsB = 0.0f;
#pragma unroll
        for (int in = 0; in < 8; in++) {
            float p0 = __expf(sacc[in][0] - mnA);
            float p1 = __expf(sacc[in][1] - mnA);
            float p2 = __expf(sacc[in][2] - mnB);
            float p3 = __expf(sacc[in][3] - mnB);
            rsA += p0 + p1; rsB += p2 + p3;
            int col = in * 8 + tg * 2;
            *reinterpret_cast<float2*>(&ps[rA * QS_STR + col]) =
                make_float2(to_tf32(p0), to_tf32(p1));
            *reinterpret_cast<float2*>(&ps[rB * QS_STR + col]) =
                make_float2(to_tf32(p2), to_tf32(p3));
        }
#pragma unroll
        for (int msk = 1; msk < 4; msk <<= 1) {
            rsA += __shfl_xor_sync(0xffffffffu, rsA, msk);
            rsB += __shfl_xor_sync(0xffffffffu, rsB, msk);
        }
        lA = lA * facA + rsA;
        lB = lB * facB + rsB;
#pragma unroll
        for (int in = 0; in < 8; in++) {
            oacc[in][0] *= facA; oacc[in][1] *= facA;
            oacc[in][2] *= facB; oacc[in][3] *= facB;
        }
        __syncthreads();   // ps visible

        // ---- O += P V ----
#pragma unroll
        for (int k8 = 0; k8 < 8; k8++) {
            const int kk = k8 * 8 + tg;
            uint32_t a0 = __float_as_uint(ps[rA * QS_STR + kk]);
            uint32_t a1 = __float_as_uint(ps[rB * QS_STR + kk]);
            uint32_t a2 = __float_as_uint(ps[rA * QS_STR + kk + 4]);
            uint32_t a3 = __float_as_uint(ps[rB * QS_STR + kk + 4]);
#pragma unroll
            for (int in = 0; in < 8; in++) {
                uint32_t b0 = __float_as_uint(vs[kk * VS_STR + in * 8 + g]);
                uint32_t b1 = __float_as_uint(vs[(kk + 4) * VS_STR + in * 8 + g]);
                mma_tf32(oacc[in], a0, a1, a2, a3, b0, b1);
            }
        }
        __syncthreads();   // PV reads of buf b + ps done (protects next iter's writes)
    }

    // ---- epilogue (tf32 values for proj A operand) ----
    const float invA = 1.0f / lA, invB = 1.0f / lB;
    const int bb = bh >> 4, hh = bh & 15;
    const int rowA = qt * 64 + rA;
#pragma unroll
    for (int in = 0; in < 8; in++) {
        int col = hh * 64 + in * 8 + tg * 2;
        *reinterpret_cast<float2*>(&g_att[(size_t)(bb * TT + rowA) * CC + col]) =
            make_float2(to_tf32(oacc[in][0] * invA), to_tf32(oacc[in][1] * invA));
        *reinterpret_cast<float2*>(&g_att[(size_t)(bb * TT + rowA + 8) * CC + col]) =
            make_float2(to_tf32(oacc[in][2] * invB), to_tf32(oacc[in][3] * invB));
    }
}

// ============================================================
extern "C" void kernel_launch(void* const* d_in, const int* in_sizes, int n_in,
                              void* d_out, int out_size)
{
    const float* x  = (const float*)d_in[0];
    const float* Wq = (const float*)d_in[1];
    const float* Wk = (const float*)d_in[2];
    const float* Wv = (const float*)d_in[3];
    const float* Wo = (const float*)d_in[4];
    const float* bo = (const float*)d_in[5];
    float* out = (float*)d_out;

    cudaFuncSetAttribute(gemm_mma<0>, cudaFuncAttributeMaxDynamicSharedMemorySize, GEMM_SMEM);
    cudaFuncSetAttribute(gemm_mma<1>, cudaFuncAttributeMaxDynamicSharedMemorySize, GEMM_SMEM);
    cudaFuncSetAttribute(attn_kernel, cudaFuncAttributeMaxDynamicSharedMemorySize, ATTN_SMEM);

    float* g_xc_p;  cudaGetSymbolAddress((void**)&g_xc_p, g_xc);
    float* g_Wp_p;  cudaGetSymbolAddress((void**)&g_Wp_p, g_Wp);

    conv_tf32<<<M_TOT * CC / 1024, 256>>>((const float4*)x, (float4*)g_xc_p);
    conv_tf32<<<CC * CC / 1024, 256>>>((const float4*)Wo, (float4*)g_Wp_p);
    wt_kernel<<<dim3(32, 32, 3), dim3(32, 8)>>>(Wq, Wk, Wv);
    gemm_mma<0><<<dim3(M_TOT / 128, 24), 256, GEMM_SMEM>>>(nullptr, nullptr, nullptr);
    attn_kernel<<<dim3(TT / 64, BB * HH), 128, ATTN_SMEM>>>();
    gemm_mma<1><<<dim3(M_TOT / 128, 8), 256, GEMM_SMEM>>>(g_Wp_p, bo, out);
}